// round 13
// baseline (speedup 1.0000x reference)
#include <cuda_runtime.h>
#include <cuda_fp16.h>
#include <math.h>
#include <stdint.h>

// ---------------- problem constants ----------------
#define BB   16
#define TT   32
#define NN_  512
#define CC   128
#define HH   128
#define HLL  512
#define G4   2048
#define DD   65536
#define TNH  ((long)TT*NN_*HH)
#define EPSN 1e-5f
#define SPLITK0 16
#define SPLITK1 4
#define LBLK 128
#define LTHR 256

// ---------------- device scratch ----------------
__device__ float g_d[NN_];
__device__ float g_tmp[BB*TT*NN_*HH];            // GN inputs; then split-K partials
__device__ float g_Z0[(long)BB*TT*G4];
__device__ float g_Z1[(long)BB*TT*G4];
__device__ __align__(16) float g_hA0[BB*HLL], g_hB0[BB*HLL];   // [HLL][BB]
__device__ __align__(16) float g_hA1[BB*HLL], g_hB1[BB*HLL];
__device__ unsigned g_bars[2];

__device__ __half g_x16  [BB*TT*NN_*CC];
__device__ __half g_hw16 [BB*TT*NN_*HH];
__device__ __half g_h116 [BB*TT*NN_*HH];
__device__ __half g_h216 [BB*TT*NN_*HH];
__device__ __half g_W116 [TT*CC*HH];
__device__ __half g_W216 [TT*HH*HH];
__device__ __half g_Wih116[G4*HLL];
__device__ __half g_M16  [NN_*NN_];
__device__ __half g_y016 [BB*TT*HLL];

// ---------------- helpers ----------------
__device__ __forceinline__ float sigf(float x) { return 1.0f/(1.0f+expf(-x)); }
__device__ __forceinline__ void cp16(uint32_t saddr, const void* g) {
    asm volatile("cp.async.cg.shared.global [%0], [%1], 16;" :: "r"(saddr), "l"(g));
}
__device__ __forceinline__ void stcg(float* p, float v) {
    asm volatile("st.global.cg.f32 [%0], %1;" :: "l"(p), "f"(v));
}
__device__ __forceinline__ float4 ldcg4(const float4* p) {
    float4 v;
    asm volatile("ld.global.cg.v4.f32 {%0,%1,%2,%3}, [%4];"
                 : "=f"(v.x), "=f"(v.y), "=f"(v.z), "=f"(v.w) : "l"(p));
    return v;
}
__device__ __forceinline__ void ldm_x4(uint32_t* r, uint32_t a) {
    asm volatile("ldmatrix.sync.aligned.m8n8.x4.shared.b16 {%0,%1,%2,%3}, [%4];"
                 : "=r"(r[0]), "=r"(r[1]), "=r"(r[2]), "=r"(r[3]) : "r"(a));
}
__device__ __forceinline__ void ldm_x4t(uint32_t* r, uint32_t a) {
    asm volatile("ldmatrix.sync.aligned.m8n8.x4.trans.shared.b16 {%0,%1,%2,%3}, [%4];"
                 : "=r"(r[0]), "=r"(r[1]), "=r"(r[2]), "=r"(r[3]) : "r"(a));
}
__device__ __forceinline__ void mma16816(float* d, const uint32_t* a, const uint32_t* b) {
    asm volatile("mma.sync.aligned.m16n8k16.row.col.f32.f16.f16.f32 "
                 "{%0,%1,%2,%3},{%4,%5,%6,%7},{%8,%9},{%0,%1,%2,%3};"
                 : "+f"(d[0]), "+f"(d[1]), "+f"(d[2]), "+f"(d[3])
                 : "r"(a[0]), "r"(a[1]), "r"(a[2]), "r"(a[3]), "r"(b[0]), "r"(b[1]));
}
__device__ __forceinline__ uint32_t packh2(float lo, float hi) {
    uint32_t r; asm("cvt.rn.f16x2.f32 %0, %2, %1;" : "=r"(r) : "f"(lo), "f"(hi)); return r;
}
__device__ __forceinline__ float2 lds64(uint32_t a) {
    float2 v; asm volatile("ld.shared.v2.f32 {%0,%1}, [%2];" : "=f"(v.x), "=f"(v.y) : "r"(a));
    return v;
}

// ---------------- fp32 -> fp16 ----------------
__global__ void f2h_kernel(const float* __restrict__ s, __half* __restrict__ d, long n) {
    long i = ((long)blockIdx.x*blockDim.x + threadIdx.x)*4;
    if (i < n) {
        float4 v = *(const float4*)&s[i];
        *(__half2*)&d[i]   = __floats2half2_rn(v.x, v.y);
        *(__half2*)&d[i+2] = __floats2half2_rn(v.z, v.w);
    }
}

// ---------------- graph normalization matrix ----------------
__global__ void deg_kernel(const float* __restrict__ adj, float* __restrict__ d) {
    int i = blockIdx.x*blockDim.x + threadIdx.x;
    if (i < NN_) {
        float s = 1.0f;
        for (int j = 0; j < NN_; j++) s += adj[(long)j*NN_ + i];
        d[i] = rsqrtf(s);
    }
}
__global__ void buildM_kernel(const float* __restrict__ adj, const float* __restrict__ d,
                              __half* __restrict__ M16) {
    int idx = blockIdx.x*blockDim.x + threadIdx.x;
    if (idx < NN_*NN_) {
        int j = idx >> 9, i = idx & (NN_-1);
        float a = adj[idx] + (i == j ? 1.0f : 0.0f);
        M16[idx] = __float2half(d[j]*a*d[i]);
    }
}

// ============================================================================
// FP16 GEMM (R9/R12): CTA 128x128x64, 8 warps of 64x32, 3-stage cp.async,
// ldmatrix fragments, mma.m16n8k16, fp32 accum. 2 CTAs/SM.
// ============================================================================
#define HBM 128
#define HBN 128
#define HBK 64
#define HKP 72
#define HNP 136
#define HSA (HBM*HKP)
#define HSB 9216
#define HSTG ((HSA+HSB)*2)
#define HSMEM (3*HSTG)

extern __shared__ char hsm[];

template<bool BNN>
__global__ void __launch_bounds__(256, 2)
hgemm(const __half* __restrict__ Ab, const __half* __restrict__ Bb,
      const float* __restrict__ biasb, float* __restrict__ C32b, __half* __restrict__ C16b,
      int M, int N, int K,
      long sA, int modA, long sB, int modB, long sBias, int modBias,
      long sC, int splitK, long sSplit)
{
    int z = blockIdx.z;
    int batch = z / splitK, split = z - batch*splitK;
    const __half* A = Ab + (long)(batch % modA)*sA;
    const __half* B = Bb + (long)(batch % modB)*sB;
    const float* bias = biasb ? biasb + (long)(batch % modBias)*sBias : nullptr;
    float* C32 = C32b ? C32b + (long)batch*sC + (long)split*sSplit : nullptr;
    __half* C16 = C16b ? C16b + (long)batch*sC : nullptr;

    int kchunk = K/splitK, kbeg = split*kchunk, nk = kchunk/HBK;
    uint32_t sm = (uint32_t)__cvta_generic_to_shared(hsm);

    int tid = threadIdx.x, lane = tid & 31, warp = tid >> 5;
    int wm = (warp & 1)*64, wn = (warp >> 1)*32;
    int m0 = blockIdx.y*HBM, n0 = blockIdx.x*HBN;

    float acc[4][4][4];
    #pragma unroll
    for (int i = 0; i < 4; i++)
        #pragma unroll
        for (int j = 0; j < 4; j++)
            #pragma unroll
            for (int k = 0; k < 4; k++) acc[i][j][k] = 0.0f;

    int a_m[4], a_kc[4], b0i[4], b1i[4];
    #pragma unroll
    for (int i = 0; i < 4; i++) {
        int idx = tid + i*256;
        a_m[i] = idx >> 3; a_kc[i] = idx & 7;
        if (BNN) { b0i[i] = idx >> 4; b1i[i] = idx & 15; }
        else     { b0i[i] = idx >> 3; b1i[i] = idx & 7; }
    }

    auto issue = [&](int s, int kt) {
        int kg = kbeg + kt*HBK;
        uint32_t ba = sm + (uint32_t)s*HSTG;
        uint32_t bb = ba + HSA*2;
        #pragma unroll
        for (int i = 0; i < 4; i++)
            cp16(ba + (uint32_t)(a_m[i]*HKP + a_kc[i]*8)*2,
                 &A[(long)(m0 + a_m[i])*K + kg + a_kc[i]*8]);
        #pragma unroll
        for (int i = 0; i < 4; i++) {
            if (BNN)
                cp16(bb + (uint32_t)(b0i[i]*HNP + b1i[i]*8)*2,
                     &B[(long)(kg + b0i[i])*N + n0 + b1i[i]*8]);
            else
                cp16(bb + (uint32_t)(b0i[i]*HKP + b1i[i]*8)*2,
                     &B[(long)(n0 + b0i[i])*K + kg + b1i[i]*8]);
        }
    };

    issue(0, 0); asm volatile("cp.async.commit_group;");
    issue(1, 1); asm volatile("cp.async.commit_group;");

    uint32_t aoff[4];
    #pragma unroll
    for (int mt = 0; mt < 4; mt++)
        aoff[mt] = (uint32_t)((wm + mt*16 + (lane & 15))*HKP + (lane >> 4)*8)*2;
    int quad = lane >> 3;
    uint32_t boff[2];
    #pragma unroll
    for (int p = 0; p < 2; p++) {
        if (BNN)
            boff[p] = (uint32_t)(((quad & 1)*8 + (lane & 7))*HNP
                      + wn + p*16 + (quad >> 1)*8)*2;
        else
            boff[p] = (uint32_t)((wn + p*16 + (quad >> 1)*8 + (lane & 7))*HKP
                      + (quad & 1)*8)*2;
    }

    for (int kt = 0; kt < nk; kt++) {
        asm volatile("cp.async.wait_group 1;");
        __syncthreads();
        if (kt + 2 < nk) issue((kt + 2) % 3, kt + 2);
        asm volatile("cp.async.commit_group;");

        uint32_t sa = sm + (uint32_t)(kt % 3)*HSTG;
        uint32_t sb = sa + HSA*2;

        #pragma unroll
        for (int ks = 0; ks < 4; ks++) {
            uint32_t af[4][4];
            #pragma unroll
            for (int mt = 0; mt < 4; mt++) ldm_x4(af[mt], sa + aoff[mt] + ks*32);
            uint32_t bf[4][2];
            #pragma unroll
            for (int p = 0; p < 2; p++) {
                uint32_t r[4];
                if (BNN) ldm_x4t(r, sb + boff[p] + (uint32_t)ks*16*HNP*2);
                else     ldm_x4 (r, sb + boff[p] + ks*32);
                bf[p*2][0] = r[0]; bf[p*2][1] = r[1];
                bf[p*2+1][0] = r[2]; bf[p*2+1][1] = r[3];
            }
            #pragma unroll
            for (int mt = 0; mt < 4; mt++)
                #pragma unroll
                for (int nt = 0; nt < 4; nt++)
                    mma16816(acc[mt][nt], af[mt], bf[nt]);
        }
    }

    #pragma unroll
    for (int nt = 0; nt < 4; nt++) {
        int c0 = n0 + wn + nt*8 + (lane & 3)*2;
        float bv0 = bias ? bias[c0] : 0.0f;
        float bv1 = bias ? bias[c0+1] : 0.0f;
        #pragma unroll
        for (int mt = 0; mt < 4; mt++) {
            int r = m0 + wm + mt*16 + (lane >> 2);
            float v00 = acc[mt][nt][0] + bv0, v01 = acc[mt][nt][1] + bv1;
            float v10 = acc[mt][nt][2] + bv0, v11 = acc[mt][nt][3] + bv1;
            if (C16) {
                *(__half2*)&C16[(long)r*N + c0]     = __floats2half2_rn(v00, v01);
                *(__half2*)&C16[(long)(r+8)*N + c0] = __floats2half2_rn(v10, v11);
            } else {
                *(float2*)&C32[(long)r*N + c0]     = make_float2(v00, v01);
                *(float2*)&C32[(long)(r+8)*N + c0] = make_float2(v10, v11);
            }
        }
    }
}

// ============================================================================
// Z0 GEMM with fp32 B (Wih0 read directly; no convert pass).
// A fp16 128x64/stage (ldmatrix); B fp32 128x64/stage, packed to fp16
// fragments via lds64+cvt (layout verified correct in R10).
// 2-stage pipeline, 104 KB smem -> 2 CTAs/SM (fixes R10's occupancy failure).
// ============================================================================
#define ZKP 68                          // fp32 B k-stride (words)
#define ZSA (HBM*HKP*2)                 // 18432 B
#define ZSB (HBN*ZKP*4)                 // 34816 B
#define ZSTG (ZSA + ZSB)                // 53248 B
#define ZSMEM (2*ZSTG)                  // 106496 B

__global__ void __launch_bounds__(256, 2)
hgemm_zf32(const __half* __restrict__ A, const float* __restrict__ B,
           float* __restrict__ Cb,
           int M, int N, int K, int splitK, long sSplit)
{
    int split = blockIdx.z;
    float* C = Cb + (long)split*sSplit;
    int kchunk = K/splitK, kbeg = split*kchunk, nk = kchunk/HBK;   // nk = 64
    uint32_t sm = (uint32_t)__cvta_generic_to_shared(hsm);

    int tid = threadIdx.x, lane = tid & 31, warp = tid >> 5;
    int wm = (warp & 1)*64, wn = (warp >> 1)*32;
    int m0 = blockIdx.y*HBM, n0 = blockIdx.x*HBN;

    float acc[4][4][4];
    #pragma unroll
    for (int i = 0; i < 4; i++)
        #pragma unroll
        for (int j = 0; j < 4; j++)
            #pragma unroll
            for (int k = 0; k < 4; k++) acc[i][j][k] = 0.0f;

    int a_m[4], a_kc[4];
    #pragma unroll
    for (int i = 0; i < 4; i++) { int idx = tid + i*256; a_m[i] = idx >> 3; a_kc[i] = idx & 7; }

    auto issue = [&](int s, int kt) {
        int kg = kbeg + kt*HBK;
        uint32_t ba = sm + (uint32_t)s*ZSTG;
        uint32_t bb = ba + ZSA;
        #pragma unroll
        for (int i = 0; i < 4; i++)
            cp16(ba + (uint32_t)(a_m[i]*HKP + a_kc[i]*8)*2,
                 &A[(long)(m0 + a_m[i])*K + kg + a_kc[i]*8]);
        #pragma unroll
        for (int i = 0; i < 8; i++) {
            int idx = tid + i*256;
            int n = idx >> 4, kc = idx & 15;
            cp16(bb + (uint32_t)(n*ZKP + kc*4)*4,
                 &B[(long)(n0 + n)*K + kg + kc*4]);
        }
    };

    issue(0, 0); asm volatile("cp.async.commit_group;");

    uint32_t aoff[4];
    #pragma unroll
    for (int mt = 0; mt < 4; mt++)
        aoff[mt] = (uint32_t)((wm + mt*16 + (lane & 15))*HKP + (lane >> 4)*8)*2;
    uint32_t bbase = (uint32_t)(((lane >> 2))*ZKP + (lane & 3)*2)*4;

    for (int kt = 0; kt < nk; kt++) {
        if (kt + 1 < nk) { issue((kt + 1) & 1, kt + 1); asm volatile("cp.async.commit_group;"); }
        if (kt + 1 < nk) { asm volatile("cp.async.wait_group 1;"); }
        else             { asm volatile("cp.async.wait_group 0;"); }
        __syncthreads();

        uint32_t sa = sm + (uint32_t)(kt & 1)*ZSTG;
        uint32_t sb = sa + ZSA;

        #pragma unroll
        for (int ks = 0; ks < 4; ks++) {
            uint32_t af[4][4];
            #pragma unroll
            for (int mt = 0; mt < 4; mt++) ldm_x4(af[mt], sa + aoff[mt] + ks*32);
            uint32_t bf[4][2];
            #pragma unroll
            for (int nt = 0; nt < 4; nt++) {
                uint32_t a0 = sb + bbase + (uint32_t)((wn + nt*8)*ZKP + ks*16)*4;
                float2 p0 = lds64(a0);
                float2 p1 = lds64(a0 + 8*4);
                bf[nt][0] = packh2(p0.x, p0.y);
                bf[nt][1] = packh2(p1.x, p1.y);
            }
            #pragma unroll
            for (int mt = 0; mt < 4; mt++)
                #pragma unroll
                for (int nt = 0; nt < 4; nt++)
                    mma16816(acc[mt][nt], af[mt], bf[nt]);
        }
        __syncthreads();   // compute done before next iter's issue overwrites this buffer
    }

    #pragma unroll
    for (int nt = 0; nt < 4; nt++) {
        int c0 = n0 + wn + nt*8 + (lane & 3)*2;
        #pragma unroll
        for (int mt = 0; mt < 4; mt++) {
            int r = m0 + wm + mt*16 + (lane >> 2);
            *(float2*)&C[(long)r*N + c0]     = make_float2(acc[mt][nt][0], acc[mt][nt][1]);
            *(float2*)&C[(long)(r+8)*N + c0] = make_float2(acc[mt][nt][2], acc[mt][nt][3]);
        }
    }
}

// ---------------- split-K reduce + bias ----------------
__global__ void reduce_bias_kernel(const float* __restrict__ P, const float* __restrict__ bias,
                                   float* __restrict__ Z, long total, long stride, int splits)
{
    long idx = (long)blockIdx.x*blockDim.x + threadIdx.x;
    if (idx >= total) return;
    float s = bias[idx & (G4-1)];
    #pragma unroll 8
    for (int i = 0; i < splits; i++) s += P[(long)i*stride + idx];
    Z[idx] = s;
}

// ---------------- GraphNorm + residual + ReLU (fp32 or fp16 residual) ----------------
template<bool RES16>
__global__ void graphnorm_kernel(const float* __restrict__ hraw,
                                 const float* __restrict__ res32,
                                 const __half* __restrict__ res16,
                                 const float* __restrict__ w, const float* __restrict__ bias,
                                 const float* __restrict__ ms,
                                 __half* __restrict__ out16)
{
    long p = (long)blockIdx.x*blockDim.x + threadIdx.x;
    if (p >= TNH) return;
    int h = (int)(p & (HH-1));
    float v[BB];
    float mean = 0.0f;
    #pragma unroll
    for (int b = 0; b < BB; b++) { v[b] = hraw[(long)b*TNH + p]; mean += v[b]; }
    mean *= (1.0f/BB);
    float msv = ms[h], var = 0.0f;
    #pragma unroll
    for (int b = 0; b < BB; b++) { v[b] -= msv*mean; var += v[b]*v[b]; }
    var *= (1.0f/BB);
    float inv = rsqrtf(var + EPSN);
    float wv = w[h]*inv, bv = bias[h];
    #pragma unroll
    for (int b = 0; b < BB; b++) {
        float rr = RES16 ? __half2float(res16[(long)b*TNH + p]) : res32[(long)b*TNH + p];
        float r = fmaxf(wv*v[b] + bv + rr, 0.0f);
        out16[(long)b*TNH + p] = __float2half(r);
    }
}

// ---------------- zero barrier counters ----------------
__global__ void zero_bars_kernel(unsigned* bars) {
    if (threadIdx.x < 2) bars[threadIdx.x] = 0u;
}

// ============================================================================
// Persistent LSTM (proven sync: st.cg -> __threadfence -> atomicAdd +
// volatile poll -> __syncthreads -> ld.cg reload). Last step skips barrier.
// ============================================================================
template<bool WRITE_Y>
__global__ void __launch_bounds__(LTHR, 1)
lstm_persistent(const float* __restrict__ Z,
                const float* __restrict__ Whh,
                const float* __restrict__ bhh,
                float* __restrict__ bufA, float* __restrict__ bufB,
                __half* __restrict__ y16,
                unsigned* __restrict__ bar)
{
    __shared__ float hs[HLL][BB];
    __shared__ float red[8*16*17];
    __shared__ float gsum[16*16];

    const int t = threadIdx.x;
    const int blk = blockIdx.x;
    const int c = t & 15, sub = t >> 4;
    const int warp = t >> 5;
    const int mh_local = c & 3, gate = c >> 2;
    const int m = gate*HLL + blk*4 + mh_local;

    float w[32];
    {
        const float* wr = Whh + (long)m*HLL + sub*32;
        #pragma unroll
        for (int j = 0; j < 32; j++) w[j] = wr[j];
    }

    const int ub = t & 15;
    const int uml = (t >> 4) & 3;
    const int umh = blk*4 + uml;
    float creg = 0.0f;
    float bi = 0.f, bf = 0.f, bg = 0.f, bo = 0.f;
    if (t < 64) {
        bi = bhh[0*HLL + umh]; bf = bhh[1*HLL + umh];
        bg = bhh[2*HLL + umh]; bo = bhh[3*HLL + umh];
    }

    for (int i = t; i < HLL*BB; i += LTHR) (&hs[0][0])[i] = 0.0f;
    __syncthreads();

    unsigned target = 0;

    for (int step = 0; step < TT; step++) {
        float zi = 0.f, zf = 0.f, zg = 0.f, zo = 0.f;
        if (t < 64) {
            long zb = ((long)ub*TT + step)*G4;
            zi = __ldcs(&Z[zb + 0*HLL + umh]); zf = __ldcs(&Z[zb + 1*HLL + umh]);
            zg = __ldcs(&Z[zb + 2*HLL + umh]); zo = __ldcs(&Z[zb + 3*HLL + umh]);
        }

        float acc[BB];
        #pragma unroll
        for (int b = 0; b < BB; b++) acc[b] = 0.0f;
        #pragma unroll
        for (int j = 0; j < 32; j++) {
            float wv = w[j];
            const float* hr = &hs[sub*32 + j][0];
            #pragma unroll
            for (int b = 0; b < BB; b += 4) {
                float4 h4 = *(const float4*)&hr[b];
                acc[b+0] += wv*h4.x; acc[b+1] += wv*h4.y;
                acc[b+2] += wv*h4.z; acc[b+3] += wv*h4.w;
            }
        }
        #pragma unroll
        for (int b = 0; b < BB; b++)
            acc[b] += __shfl_down_sync(0xffffffffu, acc[b], 16);
        if ((t & 31) < 16) {
            float* rp = &red[(warp*16 + c)*17];
            #pragma unroll
            for (int b = 0; b < BB; b++) rp[b] = acc[b];
        }
        __syncthreads();
        {
            int c2 = t & 15, b2 = t >> 4;
            float s = 0.0f;
            #pragma unroll
            for (int s2 = 0; s2 < 8; s2++) s += red[(s2*16 + c2)*17 + b2];
            gsum[c2*16 + b2] = s;
        }
        __syncthreads();

        if (t < 64) {
            float gi = sigf (zi + gsum[(0*4+uml)*16 + ub] + bi);
            float gf = sigf (zf + gsum[(1*4+uml)*16 + ub] + bf);
            float gg = tanhf(zg + gsum[(2*4+uml)*16 + ub] + bg);
            float go = sigf (zo + gsum[(3*4+uml)*16 + ub] + bo);
            creg = gf*creg + gi*gg;
            float hn = go*tanhf(creg);
            float* hout = ((step+1) & 1) ? bufB : bufA;
            stcg(&hout[umh*BB + ub], hn);
            if (WRITE_Y) y16[((long)ub*TT + step)*HLL + umh] = __float2half(hn);
            __threadfence();
        }
        __syncthreads();

        if (step + 1 < TT) {
            target += LBLK;
            if (t == 0) {
                atomicAdd(bar, 1u);
                while (*(volatile unsigned*)bar < target) { }
            }
            __syncthreads();

            const float4* hin = (const float4*)(((step+1) & 1) ? bufB : bufA);
            float4* hsd = (float4*)&hs[0][0];
            #pragma unroll
            for (int q = t; q < HLL*BB/4; q += LTHR)
                hsd[q] = ldcg4(&hin[q]);
            __syncthreads();
        }
    }
}

// ---------------- final projection (h in [j][b] layout) ----------------
__global__ void proj_kernel(const float* __restrict__ h, const float* __restrict__ Wp,
                            const float* __restrict__ bp, float* __restrict__ out)
{
    int tid = threadIdx.x;
    int b = tid >> 3, o = tid & 7;
    float s = bp[o];
    const float* wr = Wp + o*HLL;
    for (int m = 0; m < HLL; m++) s += h[m*BB + b]*wr[m];
    out[b*8 + o] = s;
}

// ---------------- launch ----------------
extern "C" void kernel_launch(void* const* d_in, const int* in_sizes, int n_in,
                              void* d_out, int out_size)
{
    const float* x    = (const float*)d_in[0];
    const float* adj  = (const float*)d_in[1];
    const float* W1   = (const float*)d_in[2];
    const float* b1   = (const float*)d_in[3];
    const float* W2   = (const float*)d_in[4];
    const float* b2   = (const float*)d_in[5];
    const float* gn1w = (const float*)d_in[6];
    const float* gn1b = (const float*)d_in[7];
    const float* gn1m = (const float*)d_in[8];
    const float* gn2w = (const float*)d_in[9];
    const float* gn2b = (const float*)d_in[10];
    const float* gn2m = (const float*)d_in[11];
    const float* Wih0 = (const float*)d_in[12];
    const float* Whh0 = (const float*)d_in[13];
    const float* bih0 = (const float*)d_in[14];
    const float* bhh0 = (const float*)d_in[15];
    const float* Wih1 = (const float*)d_in[16];
    const float* Whh1 = (const float*)d_in[17];
    const float* bih1 = (const float*)d_in[18];
    const float* bhh1 = (const float*)d_in[19];
    const float* Wp   = (const float*)d_in[20];
    const float* bp   = (const float*)d_in[21];
    float* out = (float*)d_out;

    float *pD, *pTmp, *pZ0, *pZ1, *pHA0, *pHB0, *pHA1, *pHB1;
    unsigned* pBars;
    __half *pX16, *pHw16, *pH116, *pH216, *pW116, *pW216, *pWih116, *pM16, *pY016;
    cudaGetSymbolAddress((void**)&pD,     g_d);
    cudaGetSymbolAddress((void**)&pTmp,   g_tmp);
    cudaGetSymbolAddress((void**)&pZ0,    g_Z0);
    cudaGetSymbolAddress((void**)&pZ1,    g_Z1);
    cudaGetSymbolAddress((void**)&pHA0,   g_hA0);
    cudaGetSymbolAddress((void**)&pHB0,   g_hB0);
    cudaGetSymbolAddress((void**)&pHA1,   g_hA1);
    cudaGetSymbolAddress((void**)&pHB1,   g_hB1);
    cudaGetSymbolAddress((void**)&pBars,  g_bars);
    cudaGetSymbolAddress((void**)&pX16,   g_x16);
    cudaGetSymbolAddress((void**)&pHw16,  g_hw16);
    cudaGetSymbolAddress((void**)&pH116,  g_h116);
    cudaGetSymbolAddress((void**)&pH216,  g_h216);
    cudaGetSymbolAddress((void**)&pW116,  g_W116);
    cudaGetSymbolAddress((void**)&pW216,  g_W216);
    cudaGetSymbolAddress((void**)&pWih116,g_Wih116);
    cudaGetSymbolAddress((void**)&pM16,   g_M16);
    cudaGetSymbolAddress((void**)&pY016,  g_y016);

    cudaFuncSetAttribute(hgemm<true>,  cudaFuncAttributeMaxDynamicSharedMemorySize, HSMEM);
    cudaFuncSetAttribute(hgemm<false>, cudaFuncAttributeMaxDynamicSharedMemorySize, HSMEM);
    cudaFuncSetAttribute(hgemm_zf32,   cudaFuncAttributeMaxDynamicSharedMemorySize, ZSMEM);

    // converts (Wih0 NOT converted — read fp32 directly) + M + barriers
    f2h_kernel<<<32768, 256>>>(x, pX16, (long)BB*TT*NN_*CC);
    f2h_kernel<<<512, 256>>>(W1, pW116, (long)TT*CC*HH);
    f2h_kernel<<<512, 256>>>(W2, pW216, (long)TT*HH*HH);
    f2h_kernel<<<1024, 256>>>(Wih1, pWih116, (long)G4*HLL);
    deg_kernel<<<2, 256>>>(adj, pD);
    buildM_kernel<<<(NN_*NN_)/256, 256>>>(adj, pD, pM16);
    zero_bars_kernel<<<1, 32>>>(pBars);

    const long sX = (long)NN_*HH;   // 65536
    const int  BT = BB*TT;          // 512
    const long zTot = (long)BT*G4;  // 1,048,576

    // ---- GCN layer 1 ----
    hgemm<true><<<dim3(1, NN_/HBM, BT), 256, HSMEM>>>(pX16, pW116, nullptr, nullptr, pHw16,
        NN_, HH, CC, sX, BT, (long)CC*HH, TT, 0, 1, sX, 1, 0);
    hgemm<true><<<dim3(1, NN_/HBM, BT), 256, HSMEM>>>(pM16, pHw16, b1, pTmp, nullptr,
        NN_, HH, NN_, 0, 1, sX, BT, HH, TT, sX, 1, 0);
    graphnorm_kernel<false><<<(int)(TNH/256), 256>>>(pTmp, x, nullptr,
        gn1w, gn1b, gn1m, pH116);

    // ---- GCN layer 2 ----
    hgemm<true><<<dim3(1, NN_/HBM, BT), 256, HSMEM>>>(pH116, pW216, nullptr, nullptr, pHw16,
        NN_, HH, HH, sX, BT, (long)HH*HH, TT, 0, 1, sX, 1, 0);
    hgemm<true><<<dim3(1, NN_/HBM, BT), 256, HSMEM>>>(pM16, pHw16, b2, pTmp, nullptr,
        NN_, HH, NN_, 0, 1, sX, BT, HH, TT, sX, 1, 0);
    graphnorm_kernel<true><<<(int)(TNH/256), 256>>>(pTmp, nullptr, pH116,
        gn2w, gn2b, gn2m, pH216);

    // ---- LSTM layer 0: Z0 GEMM fp32-B direct (split-K=16), reduce, recurrence ----
    hgemm_zf32<<<dim3(G4/HBN, BT/HBM, SPLITK0), 256, ZSMEM>>>(pH216, Wih0, pTmp,
        BT, G4, DD, SPLITK0, zTot);
    reduce_bias_kernel<<<(int)(zTot/256), 256>>>(pTmp, bih0, pZ0, zTot, zTot, SPLITK0);
    lstm_persistent<true><<<LBLK, LTHR>>>(pZ0, Whh0, bhh0, pHA0, pHB0, pY016, pBars + 0);

    // ---- LSTM layer 1 ----
    hgemm<false><<<dim3(G4/HBN, BT/HBM, SPLITK1), 256, HSMEM>>>(pY016, pWih116, nullptr, pTmp, nullptr,
        BT, G4, HLL, 0, 1, 0, 1, 0, 1, 0, SPLITK1, zTot);
    reduce_bias_kernel<<<(int)(zTot/256), 256>>>(pTmp, bih1, pZ1, zTot, zTot, SPLITK1);
    lstm_persistent<false><<<LBLK, LTHR>>>(pZ1, Whh1, bhh1, pHA1, pHB1, nullptr, pBars + 1);

    // ---- projection ----
    proj_kernel<<<1, 128>>>(pHA1, Wp, bp, out);
}

// round 14
// speedup vs baseline: 1.0268x; 1.0268x over previous
#include <cuda_runtime.h>
#include <cuda_fp16.h>
#include <math.h>
#include <stdint.h>

// ---------------- problem constants ----------------
#define BB   16
#define TT   32
#define NN_  512
#define CC   128
#define HH   128
#define HLL  512
#define G4   2048
#define DD   65536
#define TNH  ((long)TT*NN_*HH)
#define EPSN 1e-5f
#define SPLITK0 16
#define SPLITK1 4
#define LBLK 128
#define LTHR 256
#define CVB  64            // extra z-blocks per GCN GEMM for piggyback convert

// ---------------- device scratch ----------------
__device__ float g_d[NN_];
__device__ float g_tmp[BB*TT*NN_*HH];            // GN inputs; then split-K partials
__device__ float g_Z0[(long)BB*TT*G4];
__device__ float g_Z1[(long)BB*TT*G4];
__device__ __align__(16) float g_hA0[BB*HLL], g_hB0[BB*HLL];   // [HLL][BB]
__device__ __align__(16) float g_hA1[BB*HLL], g_hB1[BB*HLL];
__device__ unsigned g_bars[2];

__device__ __half g_x16  [BB*TT*NN_*CC];
__device__ __half g_hw16 [BB*TT*NN_*HH];
__device__ __half g_h116 [BB*TT*NN_*HH];
__device__ __half g_h216 [BB*TT*NN_*HH];
__device__ __half g_W116 [TT*CC*HH];
__device__ __half g_W216 [TT*HH*HH];
__device__ __half g_Wih016[(long)G4*DD];
__device__ __half g_Wih116[G4*HLL];
__device__ __half g_M16  [NN_*NN_];
__device__ __half g_y016 [BB*TT*HLL];

// ---------------- helpers ----------------
__device__ __forceinline__ float sigf(float x) { return 1.0f/(1.0f+expf(-x)); }
__device__ __forceinline__ void cp16(uint32_t saddr, const void* g) {
    asm volatile("cp.async.cg.shared.global [%0], [%1], 16;" :: "r"(saddr), "l"(g));
}
__device__ __forceinline__ void stcg(float* p, float v) {
    asm volatile("st.global.cg.f32 [%0], %1;" :: "l"(p), "f"(v));
}
__device__ __forceinline__ float4 ldcg4(const float4* p) {
    float4 v;
    asm volatile("ld.global.cg.v4.f32 {%0,%1,%2,%3}, [%4];"
                 : "=f"(v.x), "=f"(v.y), "=f"(v.z), "=f"(v.w) : "l"(p));
    return v;
}
__device__ __forceinline__ void ldm_x4(uint32_t* r, uint32_t a) {
    asm volatile("ldmatrix.sync.aligned.m8n8.x4.shared.b16 {%0,%1,%2,%3}, [%4];"
                 : "=r"(r[0]), "=r"(r[1]), "=r"(r[2]), "=r"(r[3]) : "r"(a));
}
__device__ __forceinline__ void ldm_x4t(uint32_t* r, uint32_t a) {
    asm volatile("ldmatrix.sync.aligned.m8n8.x4.trans.shared.b16 {%0,%1,%2,%3}, [%4];"
                 : "=r"(r[0]), "=r"(r[1]), "=r"(r[2]), "=r"(r[3]) : "r"(a));
}
__device__ __forceinline__ void mma16816(float* d, const uint32_t* a, const uint32_t* b) {
    asm volatile("mma.sync.aligned.m16n8k16.row.col.f32.f16.f16.f32 "
                 "{%0,%1,%2,%3},{%4,%5,%6,%7},{%8,%9},{%0,%1,%2,%3};"
                 : "+f"(d[0]), "+f"(d[1]), "+f"(d[2]), "+f"(d[3])
                 : "r"(a[0]), "r"(a[1]), "r"(a[2]), "r"(a[3]), "r"(b[0]), "r"(b[1]));
}

// ---------------- fp32 -> fp16 ----------------
__global__ void f2h_kernel(const float* __restrict__ s, __half* __restrict__ d, long n) {
    long i = ((long)blockIdx.x*blockDim.x + threadIdx.x)*4;
    if (i < n) {
        float4 v = *(const float4*)&s[i];
        *(__half2*)&d[i]   = __floats2half2_rn(v.x, v.y);
        *(__half2*)&d[i+2] = __floats2half2_rn(v.z, v.w);
    }
}

// ---------------- graph normalization matrix ----------------
__global__ void deg_kernel(const float* __restrict__ adj, float* __restrict__ d) {
    int i = blockIdx.x*blockDim.x + threadIdx.x;
    if (i < NN_) {
        float s = 1.0f;
        for (int j = 0; j < NN_; j++) s += adj[(long)j*NN_ + i];
        d[i] = rsqrtf(s);
    }
}
__global__ void buildM_kernel(const float* __restrict__ adj, const float* __restrict__ d,
                              __half* __restrict__ M16) {
    int idx = blockIdx.x*blockDim.x + threadIdx.x;
    if (idx < NN_*NN_) {
        int j = idx >> 9, i = idx & (NN_-1);
        float a = adj[idx] + (i == j ? 1.0f : 0.0f);
        M16[idx] = __float2half(d[j]*a*d[i]);
    }
}

// ============================================================================
// FP16 GEMM (R12 math path, unchanged): CTA 128x128x64, 8 warps of 64x32,
// 3-stage cp.async, ldmatrix, mma.m16n8k16, fp32 accum, 2 CTAs/SM.
// NEW: optional piggyback convert role — blocks with blockIdx.z >= realZ
// grid-stride convert cvtSrc[cvtBeg:cvtEnd) fp32 -> cvtDst fp16 and exit.
// ============================================================================
#define HBM 128
#define HBN 128
#define HBK 64
#define HKP 72
#define HNP 136
#define HSA (HBM*HKP)
#define HSB 9216
#define HSTG ((HSA+HSB)*2)
#define HSMEM (3*HSTG)

extern __shared__ char hsm[];

template<bool BNN>
__global__ void __launch_bounds__(256, 2)
hgemm(const __half* __restrict__ Ab, const __half* __restrict__ Bb,
      const float* __restrict__ biasb, float* __restrict__ C32b, __half* __restrict__ C16b,
      int M, int N, int K,
      long sA, int modA, long sB, int modB, long sBias, int modBias,
      long sC, int splitK, long sSplit,
      int realZ,
      const float* __restrict__ cvtSrc, __half* __restrict__ cvtDst,
      long cvtBeg, long cvtEnd)
{
    int z = blockIdx.z;
    if (cvtDst != nullptr && z >= realZ) {
        // -------- piggyback convert role --------
        long nlanes = (long)(gridDim.z - realZ)*gridDim.y*gridDim.x;
        long lane = (long)(z - realZ)*gridDim.y*gridDim.x
                  + (long)blockIdx.y*gridDim.x + blockIdx.x;
        long i = cvtBeg + (lane*256 + threadIdx.x)*4;
        long stride = nlanes*256*4;
        for (; i < cvtEnd; i += stride) {
            float4 v = *(const float4*)&cvtSrc[i];
            *(__half2*)&cvtDst[i]   = __floats2half2_rn(v.x, v.y);
            *(__half2*)&cvtDst[i+2] = __floats2half2_rn(v.z, v.w);
        }
        return;
    }

    int batch = z / splitK, split = z - batch*splitK;
    const __half* A = Ab + (long)(batch % modA)*sA;
    const __half* B = Bb + (long)(batch % modB)*sB;
    const float* bias = biasb ? biasb + (long)(batch % modBias)*sBias : nullptr;
    float* C32 = C32b ? C32b + (long)batch*sC + (long)split*sSplit : nullptr;
    __half* C16 = C16b ? C16b + (long)batch*sC : nullptr;

    int kchunk = K/splitK, kbeg = split*kchunk, nk = kchunk/HBK;
    uint32_t sm = (uint32_t)__cvta_generic_to_shared(hsm);

    int tid = threadIdx.x, lane = tid & 31, warp = tid >> 5;
    int wm = (warp & 1)*64, wn = (warp >> 1)*32;
    int m0 = blockIdx.y*HBM, n0 = blockIdx.x*HBN;

    float acc[4][4][4];
    #pragma unroll
    for (int i = 0; i < 4; i++)
        #pragma unroll
        for (int j = 0; j < 4; j++)
            #pragma unroll
            for (int k = 0; k < 4; k++) acc[i][j][k] = 0.0f;

    int a_m[4], a_kc[4], b0i[4], b1i[4];
    #pragma unroll
    for (int i = 0; i < 4; i++) {
        int idx = tid + i*256;
        a_m[i] = idx >> 3; a_kc[i] = idx & 7;
        if (BNN) { b0i[i] = idx >> 4; b1i[i] = idx & 15; }
        else     { b0i[i] = idx >> 3; b1i[i] = idx & 7; }
    }

    auto issue = [&](int s, int kt) {
        int kg = kbeg + kt*HBK;
        uint32_t ba = sm + (uint32_t)s*HSTG;
        uint32_t bb = ba + HSA*2;
        #pragma unroll
        for (int i = 0; i < 4; i++)
            cp16(ba + (uint32_t)(a_m[i]*HKP + a_kc[i]*8)*2,
                 &A[(long)(m0 + a_m[i])*K + kg + a_kc[i]*8]);
        #pragma unroll
        for (int i = 0; i < 4; i++) {
            if (BNN)
                cp16(bb + (uint32_t)(b0i[i]*HNP + b1i[i]*8)*2,
                     &B[(long)(kg + b0i[i])*N + n0 + b1i[i]*8]);
            else
                cp16(bb + (uint32_t)(b0i[i]*HKP + b1i[i]*8)*2,
                     &B[(long)(n0 + b0i[i])*K + kg + b1i[i]*8]);
        }
    };

    issue(0, 0); asm volatile("cp.async.commit_group;");
    issue(1, 1); asm volatile("cp.async.commit_group;");

    uint32_t aoff[4];
    #pragma unroll
    for (int mt = 0; mt < 4; mt++)
        aoff[mt] = (uint32_t)((wm + mt*16 + (lane & 15))*HKP + (lane >> 4)*8)*2;
    int quad = lane >> 3;
    uint32_t boff[2];
    #pragma unroll
    for (int p = 0; p < 2; p++) {
        if (BNN)
            boff[p] = (uint32_t)(((quad & 1)*8 + (lane & 7))*HNP
                      + wn + p*16 + (quad >> 1)*8)*2;
        else
            boff[p] = (uint32_t)((wn + p*16 + (quad >> 1)*8 + (lane & 7))*HKP
                      + (quad & 1)*8)*2;
    }

    for (int kt = 0; kt < nk; kt++) {
        asm volatile("cp.async.wait_group 1;");
        __syncthreads();
        if (kt + 2 < nk) issue((kt + 2) % 3, kt + 2);
        asm volatile("cp.async.commit_group;");

        uint32_t sa = sm + (uint32_t)(kt % 3)*HSTG;
        uint32_t sb = sa + HSA*2;

        #pragma unroll
        for (int ks = 0; ks < 4; ks++) {
            uint32_t af[4][4];
            #pragma unroll
            for (int mt = 0; mt < 4; mt++) ldm_x4(af[mt], sa + aoff[mt] + ks*32);
            uint32_t bf[4][2];
            #pragma unroll
            for (int p = 0; p < 2; p++) {
                uint32_t r[4];
                if (BNN) ldm_x4t(r, sb + boff[p] + (uint32_t)ks*16*HNP*2);
                else     ldm_x4 (r, sb + boff[p] + ks*32);
                bf[p*2][0] = r[0]; bf[p*2][1] = r[1];
                bf[p*2+1][0] = r[2]; bf[p*2+1][1] = r[3];
            }
            #pragma unroll
            for (int mt = 0; mt < 4; mt++)
                #pragma unroll
                for (int nt = 0; nt < 4; nt++)
                    mma16816(acc[mt][nt], af[mt], bf[nt]);
        }
    }

    #pragma unroll
    for (int nt = 0; nt < 4; nt++) {
        int c0 = n0 + wn + nt*8 + (lane & 3)*2;
        float bv0 = bias ? bias[c0] : 0.0f;
        float bv1 = bias ? bias[c0+1] : 0.0f;
        #pragma unroll
        for (int mt = 0; mt < 4; mt++) {
            int r = m0 + wm + mt*16 + (lane >> 2);
            float v00 = acc[mt][nt][0] + bv0, v01 = acc[mt][nt][1] + bv1;
            float v10 = acc[mt][nt][2] + bv0, v11 = acc[mt][nt][3] + bv1;
            if (C16) {
                *(__half2*)&C16[(long)r*N + c0]     = __floats2half2_rn(v00, v01);
                *(__half2*)&C16[(long)(r+8)*N + c0] = __floats2half2_rn(v10, v11);
            } else {
                *(float2*)&C32[(long)r*N + c0]     = make_float2(v00, v01);
                *(float2*)&C32[(long)(r+8)*N + c0] = make_float2(v10, v11);
            }
        }
    }
}

// ---------------- split-K reduce + bias ----------------
__global__ void reduce_bias_kernel(const float* __restrict__ P, const float* __restrict__ bias,
                                   float* __restrict__ Z, long total, long stride, int splits)
{
    long idx = (long)blockIdx.x*blockDim.x + threadIdx.x;
    if (idx >= total) return;
    float s = bias[idx & (G4-1)];
    #pragma unroll 8
    for (int i = 0; i < splits; i++) s += P[(long)i*stride + idx];
    Z[idx] = s;
}

// ---------------- GraphNorm + residual + ReLU (fp32 or fp16 residual) ----------------
template<bool RES16>
__global__ void graphnorm_kernel(const float* __restrict__ hraw,
                                 const float* __restrict__ res32,
                                 const __half* __restrict__ res16,
                                 const float* __restrict__ w, const float* __restrict__ bias,
                                 const float* __restrict__ ms,
                                 __half* __restrict__ out16)
{
    long p = (long)blockIdx.x*blockDim.x + threadIdx.x;
    if (p >= TNH) return;
    int h = (int)(p & (HH-1));
    float v[BB];
    float mean = 0.0f;
    #pragma unroll
    for (int b = 0; b < BB; b++) { v[b] = hraw[(long)b*TNH + p]; mean += v[b]; }
    mean *= (1.0f/BB);
    float msv = ms[h], var = 0.0f;
    #pragma unroll
    for (int b = 0; b < BB; b++) { v[b] -= msv*mean; var += v[b]*v[b]; }
    var *= (1.0f/BB);
    float inv = rsqrtf(var + EPSN);
    float wv = w[h]*inv, bv = bias[h];
    #pragma unroll
    for (int b = 0; b < BB; b++) {
        float rr = RES16 ? __half2float(res16[(long)b*TNH + p]) : res32[(long)b*TNH + p];
        float r = fmaxf(wv*v[b] + bv + rr, 0.0f);
        out16[(long)b*TNH + p] = __float2half(r);
    }
}

// ---------------- zero barrier counters ----------------
__global__ void zero_bars_kernel(unsigned* bars) {
    if (threadIdx.x < 2) bars[threadIdx.x] = 0u;
}

// ============================================================================
// Persistent LSTM (proven sync: st.cg -> __threadfence -> atomicAdd +
// volatile poll -> __syncthreads -> ld.cg reload). Last step skips barrier.
// ============================================================================
template<bool WRITE_Y>
__global__ void __launch_bounds__(LTHR, 1)
lstm_persistent(const float* __restrict__ Z,
                const float* __restrict__ Whh,
                const float* __restrict__ bhh,
                float* __restrict__ bufA, float* __restrict__ bufB,
                __half* __restrict__ y16,
                unsigned* __restrict__ bar)
{
    __shared__ float hs[HLL][BB];
    __shared__ float red[8*16*17];
    __shared__ float gsum[16*16];

    const int t = threadIdx.x;
    const int blk = blockIdx.x;
    const int c = t & 15, sub = t >> 4;
    const int warp = t >> 5;
    const int mh_local = c & 3, gate = c >> 2;
    const int m = gate*HLL + blk*4 + mh_local;

    float w[32];
    {
        const float* wr = Whh + (long)m*HLL + sub*32;
        #pragma unroll
        for (int j = 0; j < 32; j++) w[j] = wr[j];
    }

    const int ub = t & 15;
    const int uml = (t >> 4) & 3;
    const int umh = blk*4 + uml;
    float creg = 0.0f;
    float bi = 0.f, bf = 0.f, bg = 0.f, bo = 0.f;
    if (t < 64) {
        bi = bhh[0*HLL + umh]; bf = bhh[1*HLL + umh];
        bg = bhh[2*HLL + umh]; bo = bhh[3*HLL + umh];
    }

    for (int i = t; i < HLL*BB; i += LTHR) (&hs[0][0])[i] = 0.0f;
    __syncthreads();

    unsigned target = 0;

    for (int step = 0; step < TT; step++) {
        float zi = 0.f, zf = 0.f, zg = 0.f, zo = 0.f;
        if (t < 64) {
            long zb = ((long)ub*TT + step)*G4;
            zi = __ldcs(&Z[zb + 0*HLL + umh]); zf = __ldcs(&Z[zb + 1*HLL + umh]);
            zg = __ldcs(&Z[zb + 2*HLL + umh]); zo = __ldcs(&Z[zb + 3*HLL + umh]);
        }

        float acc[BB];
        #pragma unroll
        for (int b = 0; b < BB; b++) acc[b] = 0.0f;
        #pragma unroll
        for (int j = 0; j < 32; j++) {
            float wv = w[j];
            const float* hr = &hs[sub*32 + j][0];
            #pragma unroll
            for (int b = 0; b < BB; b += 4) {
                float4 h4 = *(const float4*)&hr[b];
                acc[b+0] += wv*h4.x; acc[b+1] += wv*h4.y;
                acc[b+2] += wv*h4.z; acc[b+3] += wv*h4.w;
            }
        }
        #pragma unroll
        for (int b = 0; b < BB; b++)
            acc[b] += __shfl_down_sync(0xffffffffu, acc[b], 16);
        if ((t & 31) < 16) {
            float* rp = &red[(warp*16 + c)*17];
            #pragma unroll
            for (int b = 0; b < BB; b++) rp[b] = acc[b];
        }
        __syncthreads();
        {
            int c2 = t & 15, b2 = t >> 4;
            float s = 0.0f;
            #pragma unroll
            for (int s2 = 0; s2 < 8; s2++) s += red[(s2*16 + c2)*17 + b2];
            gsum[c2*16 + b2] = s;
        }
        __syncthreads();

        if (t < 64) {
            float gi = sigf (zi + gsum[(0*4+uml)*16 + ub] + bi);
            float gf = sigf (zf + gsum[(1*4+uml)*16 + ub] + bf);
            float gg = tanhf(zg + gsum[(2*4+uml)*16 + ub] + bg);
            float go = sigf (zo + gsum[(3*4+uml)*16 + ub] + bo);
            creg = gf*creg + gi*gg;
            float hn = go*tanhf(creg);
            float* hout = ((step+1) & 1) ? bufB : bufA;
            stcg(&hout[umh*BB + ub], hn);
            if (WRITE_Y) y16[((long)ub*TT + step)*HLL + umh] = __float2half(hn);
            __threadfence();
        }
        __syncthreads();

        if (step + 1 < TT) {
            target += LBLK;
            if (t == 0) {
                atomicAdd(bar, 1u);
                while (*(volatile unsigned*)bar < target) { }
            }
            __syncthreads();

            const float4* hin = (const float4*)(((step+1) & 1) ? bufB : bufA);
            float4* hsd = (float4*)&hs[0][0];
            #pragma unroll
            for (int q = t; q < HLL*BB/4; q += LTHR)
                hsd[q] = ldcg4(&hin[q]);
            __syncthreads();
        }
    }
}

// ---------------- final projection (h in [j][b] layout) ----------------
__global__ void proj_kernel(const float* __restrict__ h, const float* __restrict__ Wp,
                            const float* __restrict__ bp, float* __restrict__ out)
{
    int tid = threadIdx.x;
    int b = tid >> 3, o = tid & 7;
    float s = bp[o];
    const float* wr = Wp + o*HLL;
    for (int m = 0; m < HLL; m++) s += h[m*BB + b]*wr[m];
    out[b*8 + o] = s;
}

// ---------------- launch ----------------
extern "C" void kernel_launch(void* const* d_in, const int* in_sizes, int n_in,
                              void* d_out, int out_size)
{
    const float* x    = (const float*)d_in[0];
    const float* adj  = (const float*)d_in[1];
    const float* W1   = (const float*)d_in[2];
    const float* b1   = (const float*)d_in[3];
    const float* W2   = (const float*)d_in[4];
    const float* b2   = (const float*)d_in[5];
    const float* gn1w = (const float*)d_in[6];
    const float* gn1b = (const float*)d_in[7];
    const float* gn1m = (const float*)d_in[8];
    const float* gn2w = (const float*)d_in[9];
    const float* gn2b = (const float*)d_in[10];
    const float* gn2m = (const float*)d_in[11];
    const float* Wih0 = (const float*)d_in[12];
    const float* Whh0 = (const float*)d_in[13];
    const float* bih0 = (const float*)d_in[14];
    const float* bhh0 = (const float*)d_in[15];
    const float* Wih1 = (const float*)d_in[16];
    const float* Whh1 = (const float*)d_in[17];
    const float* bih1 = (const float*)d_in[18];
    const float* bhh1 = (const float*)d_in[19];
    const float* Wp   = (const float*)d_in[20];
    const float* bp   = (const float*)d_in[21];
    float* out = (float*)d_out;

    float *pD, *pTmp, *pZ0, *pZ1, *pHA0, *pHB0, *pHA1, *pHB1;
    unsigned* pBars;
    __half *pX16, *pHw16, *pH116, *pH216, *pW116, *pW216, *pWih016, *pWih116, *pM16, *pY016;
    cudaGetSymbolAddress((void**)&pD,     g_d);
    cudaGetSymbolAddress((void**)&pTmp,   g_tmp);
    cudaGetSymbolAddress((void**)&pZ0,    g_Z0);
    cudaGetSymbolAddress((void**)&pZ1,    g_Z1);
    cudaGetSymbolAddress((void**)&pHA0,   g_hA0);
    cudaGetSymbolAddress((void**)&pHB0,   g_hB0);
    cudaGetSymbolAddress((void**)&pHA1,   g_hA1);
    cudaGetSymbolAddress((void**)&pHB1,   g_hB1);
    cudaGetSymbolAddress((void**)&pBars,  g_bars);
    cudaGetSymbolAddress((void**)&pX16,   g_x16);
    cudaGetSymbolAddress((void**)&pHw16,  g_hw16);
    cudaGetSymbolAddress((void**)&pH116,  g_h116);
    cudaGetSymbolAddress((void**)&pH216,  g_h216);
    cudaGetSymbolAddress((void**)&pW116,  g_W116);
    cudaGetSymbolAddress((void**)&pW216,  g_W216);
    cudaGetSymbolAddress((void**)&pWih016,g_Wih016);
    cudaGetSymbolAddress((void**)&pWih116,g_Wih116);
    cudaGetSymbolAddress((void**)&pM16,   g_M16);
    cudaGetSymbolAddress((void**)&pY016,  g_y016);

    cudaFuncSetAttribute(hgemm<true>,  cudaFuncAttributeMaxDynamicSharedMemorySize, HSMEM);
    cudaFuncSetAttribute(hgemm<false>, cudaFuncAttributeMaxDynamicSharedMemorySize, HSMEM);

    // small converts + M + barriers (Wih0 converted via piggyback on GCN GEMMs)
    f2h_kernel<<<32768, 256>>>(x, pX16, (long)BB*TT*NN_*CC);
    f2h_kernel<<<512, 256>>>(W1, pW116, (long)TT*CC*HH);
    f2h_kernel<<<512, 256>>>(W2, pW216, (long)TT*HH*HH);
    f2h_kernel<<<1024, 256>>>(Wih1, pWih116, (long)G4*HLL);
    deg_kernel<<<2, 256>>>(adj, pD);
    buildM_kernel<<<(NN_*NN_)/256, 256>>>(adj, pD, pM16);
    zero_bars_kernel<<<1, 32>>>(pBars);

    const long sX = (long)NN_*HH;   // 65536
    const int  BT = BB*TT;          // 512
    const long zTot = (long)BT*G4;  // 1,048,576
    const long WTOT = (long)G4*DD;  // 134,217,728 floats
    const long QTR = WTOT/4;

    // ---- GCN layer 1 (each GEMM piggybacks 1/4 of the Wih0 convert) ----
    hgemm<true><<<dim3(1, NN_/HBM, BT + CVB), 256, HSMEM>>>(pX16, pW116, nullptr, nullptr, pHw16,
        NN_, HH, CC, sX, BT, (long)CC*HH, TT, 0, 1, sX, 1, 0,
        BT, Wih0, pWih016, 0*QTR, 1*QTR);
    hgemm<true><<<dim3(1, NN_/HBM, BT + CVB), 256, HSMEM>>>(pM16, pHw16, b1, pTmp, nullptr,
        NN_, HH, NN_, 0, 1, sX, BT, HH, TT, sX, 1, 0,
        BT, Wih0, pWih016, 1*QTR, 2*QTR);
    graphnorm_kernel<false><<<(int)(TNH/256), 256>>>(pTmp, x, nullptr,
        gn1w, gn1b, gn1m, pH116);

    // ---- GCN layer 2 ----
    hgemm<true><<<dim3(1, NN_/HBM, BT + CVB), 256, HSMEM>>>(pH116, pW216, nullptr, nullptr, pHw16,
        NN_, HH, HH, sX, BT, (long)HH*HH, TT, 0, 1, sX, 1, 0,
        BT, Wih0, pWih016, 2*QTR, 3*QTR);
    hgemm<true><<<dim3(1, NN_/HBM, BT + CVB), 256, HSMEM>>>(pM16, pHw16, b2, pTmp, nullptr,
        NN_, HH, NN_, 0, 1, sX, BT, HH, TT, sX, 1, 0,
        BT, Wih0, pWih016, 3*QTR, 4*QTR);
    graphnorm_kernel<true><<<(int)(TNH/256), 256>>>(pTmp, nullptr, pH116,
        gn2w, gn2b, gn2m, pH216);

    // ---- LSTM layer 0: Z0 GEMM (split-K=16), reduce, persistent recurrence ----
    hgemm<false><<<dim3(G4/HBN, BT/HBM, SPLITK0), 256, HSMEM>>>(pH216, pWih016, nullptr, pTmp, nullptr,
        BT, G4, DD, 0, 1, 0, 1, 0, 1, 0, SPLITK0, zTot,
        SPLITK0, nullptr, nullptr, 0, 0);
    reduce_bias_kernel<<<(int)(zTot/256), 256>>>(pTmp, bih0, pZ0, zTot, zTot, SPLITK0);
    lstm_persistent<true><<<LBLK, LTHR>>>(pZ0, Whh0, bhh0, pHA0, pHB0, pY016, pBars + 0);

    // ---- LSTM layer 1 ----
    hgemm<false><<<dim3(G4/HBN, BT/HBM, SPLITK1), 256, HSMEM>>>(pY016, pWih116, nullptr, pTmp, nullptr,
        BT, G4, HLL, 0, 1, 0, 1, 0, 1, 0, SPLITK1, zTot,
        SPLITK1, nullptr, nullptr, 0, 0);
    reduce_bias_kernel<<<(int)(zTot/256), 256>>>(pTmp, bih1, pZ1, zTot, zTot, SPLITK1);
    lstm_persistent<false><<<LBLK, LTHR>>>(pZ1, Whh1, bhh1, pHA1, pHB1, nullptr, pBars + 1);

    // ---- projection ----
    proj_kernel<<<1, 128>>>(pHA1, Wp, bp, out);
}

// round 15
// speedup vs baseline: 1.0643x; 1.0365x over previous
#include <cuda_runtime.h>
#include <cuda_fp16.h>
#include <math.h>
#include <stdint.h>

// ---------------- problem constants ----------------
#define BB   16
#define TT   32
#define NN_  512
#define CC   128
#define HH   128
#define HLL  512
#define G4   2048
#define DD   65536
#define TNH  ((long)TT*NN_*HH)
#define EPSN 1e-5f
#define SPLITK0 16
#define SPLITK1 4
#define LBLK 128
#define LTHR 256
#define NBAR 8
#define BARSTR 32      // words between counters (128 B)

// ---------------- device scratch ----------------
__device__ float g_d[NN_];
__device__ float g_tmp[BB*TT*NN_*HH];            // GN inputs; then split-K partials
__device__ float g_Z0[(long)BB*TT*G4];
__device__ float g_Z1[(long)BB*TT*G4];
__device__ __align__(16) float g_hA0[BB*HLL], g_hB0[BB*HLL];   // [HLL][BB]
__device__ __align__(16) float g_hA1[BB*HLL], g_hB1[BB*HLL];
__device__ unsigned g_bars[2*NBAR*BARSTR];

__device__ __half g_x16  [BB*TT*NN_*CC];
__device__ __half g_hw16 [BB*TT*NN_*HH];
__device__ __half g_h116 [BB*TT*NN_*HH];
__device__ __half g_h216 [BB*TT*NN_*HH];
__device__ __half g_W116 [TT*CC*HH];
__device__ __half g_W216 [TT*HH*HH];
__device__ __half g_Wih016[(long)G4*DD];
__device__ __half g_Wih116[G4*HLL];
__device__ __half g_M16  [NN_*NN_];
__device__ __half g_y016 [BB*TT*HLL];

// ---------------- helpers ----------------
__device__ __forceinline__ float sigf(float x) { return 1.0f/(1.0f+expf(-x)); }
__device__ __forceinline__ void cp16(uint32_t saddr, const void* g) {
    asm volatile("cp.async.cg.shared.global [%0], [%1], 16;" :: "r"(saddr), "l"(g));
}
__device__ __forceinline__ void stcg(float* p, float v) {
    asm volatile("st.global.cg.f32 [%0], %1;" :: "l"(p), "f"(v));
}
__device__ __forceinline__ float4 ldcg4(const float4* p) {
    float4 v;
    asm volatile("ld.global.cg.v4.f32 {%0,%1,%2,%3}, [%4];"
                 : "=f"(v.x), "=f"(v.y), "=f"(v.z), "=f"(v.w) : "l"(p));
    return v;
}
__device__ __forceinline__ void ldm_x4(uint32_t* r, uint32_t a) {
    asm volatile("ldmatrix.sync.aligned.m8n8.x4.shared.b16 {%0,%1,%2,%3}, [%4];"
                 : "=r"(r[0]), "=r"(r[1]), "=r"(r[2]), "=r"(r[3]) : "r"(a));
}
__device__ __forceinline__ void ldm_x4t(uint32_t* r, uint32_t a) {
    asm volatile("ldmatrix.sync.aligned.m8n8.x4.trans.shared.b16 {%0,%1,%2,%3}, [%4];"
                 : "=r"(r[0]), "=r"(r[1]), "=r"(r[2]), "=r"(r[3]) : "r"(a));
}
__device__ __forceinline__ void mma16816(float* d, const uint32_t* a, const uint32_t* b) {
    asm volatile("mma.sync.aligned.m16n8k16.row.col.f32.f16.f16.f32 "
                 "{%0,%1,%2,%3},{%4,%5,%6,%7},{%8,%9},{%0,%1,%2,%3};"
                 : "+f"(d[0]), "+f"(d[1]), "+f"(d[2]), "+f"(d[3])
                 : "r"(a[0]), "r"(a[1]), "r"(a[2]), "r"(a[3]), "r"(b[0]), "r"(b[1]));
}

// ---------------- fp32 -> fp16 ----------------
__global__ void f2h_kernel(const float* __restrict__ s, __half* __restrict__ d, long n) {
    long i = ((long)blockIdx.x*blockDim.x + threadIdx.x)*4;
    if (i < n) {
        float4 v = *(const float4*)&s[i];
        *(__half2*)&d[i]   = __floats2half2_rn(v.x, v.y);
        *(__half2*)&d[i+2] = __floats2half2_rn(v.z, v.w);
    }
}

// ---------------- graph normalization matrix ----------------
__global__ void deg_kernel(const float* __restrict__ adj, float* __restrict__ d) {
    int i = blockIdx.x*blockDim.x + threadIdx.x;
    if (i < NN_) {
        float s = 1.0f;
        for (int j = 0; j < NN_; j++) s += adj[(long)j*NN_ + i];
        d[i] = rsqrtf(s);
    }
}
__global__ void buildM_kernel(const float* __restrict__ adj, const float* __restrict__ d,
                              __half* __restrict__ M16) {
    int idx = blockIdx.x*blockDim.x + threadIdx.x;
    if (idx < NN_*NN_) {
        int j = idx >> 9, i = idx & (NN_-1);
        float a = adj[idx] + (i == j ? 1.0f : 0.0f);
        M16[idx] = __float2half(d[j]*a*d[i]);
    }
}

// ============================================================================
// FP16 GEMM (R12, unchanged): CTA 128x128x64, 8 warps of 64x32, 3-stage
// cp.async, ldmatrix fragments, mma.m16n8k16, fp32 accum. 2 CTAs/SM.
// ============================================================================
#define HBM 128
#define HBN 128
#define HBK 64
#define HKP 72
#define HNP 136
#define HSA (HBM*HKP)
#define HSB 9216
#define HSTG ((HSA+HSB)*2)
#define HSMEM (3*HSTG)

extern __shared__ char hsm[];

template<bool BNN>
__global__ void __launch_bounds__(256, 2)
hgemm(const __half* __restrict__ Ab, const __half* __restrict__ Bb,
      const float* __restrict__ biasb, float* __restrict__ C32b, __half* __restrict__ C16b,
      int M, int N, int K,
      long sA, int modA, long sB, int modB, long sBias, int modBias,
      long sC, int splitK, long sSplit)
{
    int z = blockIdx.z;
    int batch = z / splitK, split = z - batch*splitK;
    const __half* A = Ab + (long)(batch % modA)*sA;
    const __half* B = Bb + (long)(batch % modB)*sB;
    const float* bias = biasb ? biasb + (long)(batch % modBias)*sBias : nullptr;
    float* C32 = C32b ? C32b + (long)batch*sC + (long)split*sSplit : nullptr;
    __half* C16 = C16b ? C16b + (long)batch*sC : nullptr;

    int kchunk = K/splitK, kbeg = split*kchunk, nk = kchunk/HBK;
    uint32_t sm = (uint32_t)__cvta_generic_to_shared(hsm);

    int tid = threadIdx.x, lane = tid & 31, warp = tid >> 5;
    int wm = (warp & 1)*64, wn = (warp >> 1)*32;
    int m0 = blockIdx.y*HBM, n0 = blockIdx.x*HBN;

    float acc[4][4][4];
    #pragma unroll
    for (int i = 0; i < 4; i++)
        #pragma unroll
        for (int j = 0; j < 4; j++)
            #pragma unroll
            for (int k = 0; k < 4; k++) acc[i][j][k] = 0.0f;

    int a_m[4], a_kc[4], b0i[4], b1i[4];
    #pragma unroll
    for (int i = 0; i < 4; i++) {
        int idx = tid + i*256;
        a_m[i] = idx >> 3; a_kc[i] = idx & 7;
        if (BNN) { b0i[i] = idx >> 4; b1i[i] = idx & 15; }
        else     { b0i[i] = idx >> 3; b1i[i] = idx & 7; }
    }

    auto issue = [&](int s, int kt) {
        int kg = kbeg + kt*HBK;
        uint32_t ba = sm + (uint32_t)s*HSTG;
        uint32_t bb = ba + HSA*2;
        #pragma unroll
        for (int i = 0; i < 4; i++)
            cp16(ba + (uint32_t)(a_m[i]*HKP + a_kc[i]*8)*2,
                 &A[(long)(m0 + a_m[i])*K + kg + a_kc[i]*8]);
        #pragma unroll
        for (int i = 0; i < 4; i++) {
            if (BNN)
                cp16(bb + (uint32_t)(b0i[i]*HNP + b1i[i]*8)*2,
                     &B[(long)(kg + b0i[i])*N + n0 + b1i[i]*8]);
            else
                cp16(bb + (uint32_t)(b0i[i]*HKP + b1i[i]*8)*2,
                     &B[(long)(n0 + b0i[i])*K + kg + b1i[i]*8]);
        }
    };

    issue(0, 0); asm volatile("cp.async.commit_group;");
    issue(1, 1); asm volatile("cp.async.commit_group;");

    uint32_t aoff[4];
    #pragma unroll
    for (int mt = 0; mt < 4; mt++)
        aoff[mt] = (uint32_t)((wm + mt*16 + (lane & 15))*HKP + (lane >> 4)*8)*2;
    int quad = lane >> 3;
    uint32_t boff[2];
    #pragma unroll
    for (int p = 0; p < 2; p++) {
        if (BNN)
            boff[p] = (uint32_t)(((quad & 1)*8 + (lane & 7))*HNP
                      + wn + p*16 + (quad >> 1)*8)*2;
        else
            boff[p] = (uint32_t)((wn + p*16 + (quad >> 1)*8 + (lane & 7))*HKP
                      + (quad & 1)*8)*2;
    }

    for (int kt = 0; kt < nk; kt++) {
        asm volatile("cp.async.wait_group 1;");
        __syncthreads();
        if (kt + 2 < nk) issue((kt + 2) % 3, kt + 2);
        asm volatile("cp.async.commit_group;");

        uint32_t sa = sm + (uint32_t)(kt % 3)*HSTG;
        uint32_t sb = sa + HSA*2;

        #pragma unroll
        for (int ks = 0; ks < 4; ks++) {
            uint32_t af[4][4];
            #pragma unroll
            for (int mt = 0; mt < 4; mt++) ldm_x4(af[mt], sa + aoff[mt] + ks*32);
            uint32_t bf[4][2];
            #pragma unroll
            for (int p = 0; p < 2; p++) {
                uint32_t r[4];
                if (BNN) ldm_x4t(r, sb + boff[p] + (uint32_t)ks*16*HNP*2);
                else     ldm_x4 (r, sb + boff[p] + ks*32);
                bf[p*2][0] = r[0]; bf[p*2][1] = r[1];
                bf[p*2+1][0] = r[2]; bf[p*2+1][1] = r[3];
            }
            #pragma unroll
            for (int mt = 0; mt < 4; mt++)
                #pragma unroll
                for (int nt = 0; nt < 4; nt++)
                    mma16816(acc[mt][nt], af[mt], bf[nt]);
        }
    }

    #pragma unroll
    for (int nt = 0; nt < 4; nt++) {
        int c0 = n0 + wn + nt*8 + (lane & 3)*2;
        float bv0 = bias ? bias[c0] : 0.0f;
        float bv1 = bias ? bias[c0+1] : 0.0f;
        #pragma unroll
        for (int mt = 0; mt < 4; mt++) {
            int r = m0 + wm + mt*16 + (lane >> 2);
            float v00 = acc[mt][nt][0] + bv0, v01 = acc[mt][nt][1] + bv1;
            float v10 = acc[mt][nt][2] + bv0, v11 = acc[mt][nt][3] + bv1;
            if (C16) {
                *(__half2*)&C16[(long)r*N + c0]     = __floats2half2_rn(v00, v01);
                *(__half2*)&C16[(long)(r+8)*N + c0] = __floats2half2_rn(v10, v11);
            } else {
                *(float2*)&C32[(long)r*N + c0]     = make_float2(v00, v01);
                *(float2*)&C32[(long)(r+8)*N + c0] = make_float2(v10, v11);
            }
        }
    }
}

// ---------------- split-K reduce + bias ----------------
__global__ void reduce_bias_kernel(const float* __restrict__ P, const float* __restrict__ bias,
                                   float* __restrict__ Z, long total, long stride, int splits)
{
    long idx = (long)blockIdx.x*blockDim.x + threadIdx.x;
    if (idx >= total) return;
    float s = bias[idx & (G4-1)];
    #pragma unroll 8
    for (int i = 0; i < splits; i++) s += P[(long)i*stride + idx];
    Z[idx] = s;
}

// ---------------- GraphNorm + residual + ReLU (fp32 or fp16 residual) ----------------
template<bool RES16>
__global__ void graphnorm_kernel(const float* __restrict__ hraw,
                                 const float* __restrict__ res32,
                                 const __half* __restrict__ res16,
                                 const float* __restrict__ w, const float* __restrict__ bias,
                                 const float* __restrict__ ms,
                                 __half* __restrict__ out16)
{
    long p = (long)blockIdx.x*blockDim.x + threadIdx.x;
    if (p >= TNH) return;
    int h = (int)(p & (HH-1));
    float v[BB];
    float mean = 0.0f;
    #pragma unroll
    for (int b = 0; b < BB; b++) { v[b] = hraw[(long)b*TNH + p]; mean += v[b]; }
    mean *= (1.0f/BB);
    float msv = ms[h], var = 0.0f;
    #pragma unroll
    for (int b = 0; b < BB; b++) { v[b] -= msv*mean; var += v[b]*v[b]; }
    var *= (1.0f/BB);
    float inv = rsqrtf(var + EPSN);
    float wv = w[h]*inv, bv = bias[h];
    #pragma unroll
    for (int b = 0; b < BB; b++) {
        float rr = RES16 ? __half2float(res16[(long)b*TNH + p]) : res32[(long)b*TNH + p];
        float r = fmaxf(wv*v[b] + bv + rr, 0.0f);
        out16[(long)b*TNH + p] = __float2half(r);
    }
}

// ---------------- zero barrier counters ----------------
__global__ void zero_bars_kernel(unsigned* bars) {
    int i = blockIdx.x*blockDim.x + threadIdx.x;
    if (i < 2*NBAR*BARSTR) bars[i] = 0u;
}

// ============================================================================
// Persistent LSTM. Identical to R12 except the grid barrier uses NBAR=8
// spread counters (128B apart, <=16 atomic arrivals each) with the PROVEN
// poll form: plain atomicAdd + pure C volatile reads. Ordering chain is
// unchanged: every writer thread does st.cg then __threadfence BEFORE the
// block's __syncthreads; t0's atomicAdd follows; counters are monotone so a
// (possibly stale) sum >= target implies all arrivals and, via each
// writer's fence, global visibility of all h stores.
// ============================================================================
template<bool WRITE_Y>
__global__ void __launch_bounds__(LTHR, 1)
lstm_persistent(const float* __restrict__ Z,
                const float* __restrict__ Whh,
                const float* __restrict__ bhh,
                float* __restrict__ bufA, float* __restrict__ bufB,
                __half* __restrict__ y16,
                unsigned* __restrict__ bar)
{
    __shared__ float hs[HLL][BB];
    __shared__ float red[8*16*17];
    __shared__ float gsum[16*16];

    const int t = threadIdx.x;
    const int blk = blockIdx.x;
    const int c = t & 15, sub = t >> 4;
    const int warp = t >> 5;
    const int mh_local = c & 3, gate = c >> 2;
    const int m = gate*HLL + blk*4 + mh_local;

    float w[32];
    {
        const float* wr = Whh + (long)m*HLL + sub*32;
        #pragma unroll
        for (int j = 0; j < 32; j++) w[j] = wr[j];
    }

    const int ub = t & 15;
    const int uml = (t >> 4) & 3;
    const int umh = blk*4 + uml;
    float creg = 0.0f;
    float bi = 0.f, bf = 0.f, bg = 0.f, bo = 0.f;
    if (t < 64) {
        bi = bhh[0*HLL + umh]; bf = bhh[1*HLL + umh];
        bg = bhh[2*HLL + umh]; bo = bhh[3*HLL + umh];
    }

    for (int i = t; i < HLL*BB; i += LTHR) (&hs[0][0])[i] = 0.0f;
    __syncthreads();

    unsigned target = 0;

    for (int step = 0; step < TT; step++) {
        float zi = 0.f, zf = 0.f, zg = 0.f, zo = 0.f;
        if (t < 64) {
            long zb = ((long)ub*TT + step)*G4;
            zi = __ldcs(&Z[zb + 0*HLL + umh]); zf = __ldcs(&Z[zb + 1*HLL + umh]);
            zg = __ldcs(&Z[zb + 2*HLL + umh]); zo = __ldcs(&Z[zb + 3*HLL + umh]);
        }

        float acc[BB];
        #pragma unroll
        for (int b = 0; b < BB; b++) acc[b] = 0.0f;
        #pragma unroll
        for (int j = 0; j < 32; j++) {
            float wv = w[j];
            const float* hr = &hs[sub*32 + j][0];
            #pragma unroll
            for (int b = 0; b < BB; b += 4) {
                float4 h4 = *(const float4*)&hr[b];
                acc[b+0] += wv*h4.x; acc[b+1] += wv*h4.y;
                acc[b+2] += wv*h4.z; acc[b+3] += wv*h4.w;
            }
        }
        #pragma unroll
        for (int b = 0; b < BB; b++)
            acc[b] += __shfl_down_sync(0xffffffffu, acc[b], 16);
        if ((t & 31) < 16) {
            float* rp = &red[(warp*16 + c)*17];
            #pragma unroll
            for (int b = 0; b < BB; b++) rp[b] = acc[b];
        }
        __syncthreads();
        {
            int c2 = t & 15, b2 = t >> 4;
            float s = 0.0f;
            #pragma unroll
            for (int s2 = 0; s2 < 8; s2++) s += red[(s2*16 + c2)*17 + b2];
            gsum[c2*16 + b2] = s;
        }
        __syncthreads();

        if (t < 64) {
            float gi = sigf (zi + gsum[(0*4+uml)*16 + ub] + bi);
            float gf = sigf (zf + gsum[(1*4+uml)*16 + ub] + bf);
            float gg = tanhf(zg + gsum[(2*4+uml)*16 + ub] + bg);
            float go = sigf (zo + gsum[(3*4+uml)*16 + ub] + bo);
            creg = gf*creg + gi*gg;
            float hn = go*tanhf(creg);
            float* hout = ((step+1) & 1) ? bufB : bufA;
            stcg(&hout[umh*BB + ub], hn);
            if (WRITE_Y) y16[((long)ub*TT + step)*HLL + umh] = __float2half(hn);
            __threadfence();
        }
        __syncthreads();

        if (step + 1 < TT) {
            target += LBLK;
            if (t == 0) {
                atomicAdd(&bar[(blk & (NBAR-1))*BARSTR], 1u);
                unsigned sum;
                do {
                    sum = 0;
                    #pragma unroll
                    for (int q = 0; q < NBAR; q++)
                        sum += *(volatile unsigned*)&bar[q*BARSTR];
                } while (sum < target);
            }
            __syncthreads();

            const float4* hin = (const float4*)(((step+1) & 1) ? bufB : bufA);
            float4* hsd = (float4*)&hs[0][0];
            #pragma unroll
            for (int q = t; q < HLL*BB/4; q += LTHR)
                hsd[q] = ldcg4(&hin[q]);
            __syncthreads();
        }
    }
}

// ---------------- final projection (h in [j][b] layout) ----------------
__global__ void proj_kernel(const float* __restrict__ h, const float* __restrict__ Wp,
                            const float* __restrict__ bp, float* __restrict__ out)
{
    int tid = threadIdx.x;
    int b = tid >> 3, o = tid & 7;
    float s = bp[o];
    const float* wr = Wp + o*HLL;
    for (int m = 0; m < HLL; m++) s += h[m*BB + b]*wr[m];
    out[b*8 + o] = s;
}

// ---------------- launch ----------------
extern "C" void kernel_launch(void* const* d_in, const int* in_sizes, int n_in,
                              void* d_out, int out_size)
{
    const float* x    = (const float*)d_in[0];
    const float* adj  = (const float*)d_in[1];
    const float* W1   = (const float*)d_in[2];
    const float* b1   = (const float*)d_in[3];
    const float* W2   = (const float*)d_in[4];
    const float* b2   = (const float*)d_in[5];
    const float* gn1w = (const float*)d_in[6];
    const float* gn1b = (const float*)d_in[7];
    const float* gn1m = (const float*)d_in[8];
    const float* gn2w = (const float*)d_in[9];
    const float* gn2b = (const float*)d_in[10];
    const float* gn2m = (const float*)d_in[11];
    const float* Wih0 = (const float*)d_in[12];
    const float* Whh0 = (const float*)d_in[13];
    const float* bih0 = (const float*)d_in[14];
    const float* bhh0 = (const float*)d_in[15];
    const float* Wih1 = (const float*)d_in[16];
    const float* Whh1 = (const float*)d_in[17];
    const float* bih1 = (const float*)d_in[18];
    const float* bhh1 = (const float*)d_in[19];
    const float* Wp   = (const float*)d_in[20];
    const float* bp   = (const float*)d_in[21];
    float* out = (float*)d_out;

    float *pD, *pTmp, *pZ0, *pZ1, *pHA0, *pHB0, *pHA1, *pHB1;
    unsigned* pBars;
    __half *pX16, *pHw16, *pH116, *pH216, *pW116, *pW216, *pWih016, *pWih116, *pM16, *pY016;
    cudaGetSymbolAddress((void**)&pD,     g_d);
    cudaGetSymbolAddress((void**)&pTmp,   g_tmp);
    cudaGetSymbolAddress((void**)&pZ0,    g_Z0);
    cudaGetSymbolAddress((void**)&pZ1,    g_Z1);
    cudaGetSymbolAddress((void**)&pHA0,   g_hA0);
    cudaGetSymbolAddress((void**)&pHB0,   g_hB0);
    cudaGetSymbolAddress((void**)&pHA1,   g_hA1);
    cudaGetSymbolAddress((void**)&pHB1,   g_hB1);
    cudaGetSymbolAddress((void**)&pBars,  g_bars);
    cudaGetSymbolAddress((void**)&pX16,   g_x16);
    cudaGetSymbolAddress((void**)&pHw16,  g_hw16);
    cudaGetSymbolAddress((void**)&pH116,  g_h116);
    cudaGetSymbolAddress((void**)&pH216,  g_h216);
    cudaGetSymbolAddress((void**)&pW116,  g_W116);
    cudaGetSymbolAddress((void**)&pW216,  g_W216);
    cudaGetSymbolAddress((void**)&pWih016,g_Wih016);
    cudaGetSymbolAddress((void**)&pWih116,g_Wih116);
    cudaGetSymbolAddress((void**)&pM16,   g_M16);
    cudaGetSymbolAddress((void**)&pY016,  g_y016);

    cudaFuncSetAttribute(hgemm<true>,  cudaFuncAttributeMaxDynamicSharedMemorySize, HSMEM);
    cudaFuncSetAttribute(hgemm<false>, cudaFuncAttributeMaxDynamicSharedMemorySize, HSMEM);

    // converts + M + barriers
    f2h_kernel<<<32768, 256>>>(x, pX16, (long)BB*TT*NN_*CC);
    f2h_kernel<<<512, 256>>>(W1, pW116, (long)TT*CC*HH);
    f2h_kernel<<<512, 256>>>(W2, pW216, (long)TT*HH*HH);
    f2h_kernel<<<131072, 256>>>(Wih0, pWih016, (long)G4*DD);
    f2h_kernel<<<1024, 256>>>(Wih1, pWih116, (long)G4*HLL);
    deg_kernel<<<2, 256>>>(adj, pD);
    buildM_kernel<<<(NN_*NN_)/256, 256>>>(adj, pD, pM16);
    zero_bars_kernel<<<2, 256>>>(pBars);

    const long sX = (long)NN_*HH;   // 65536
    const int  BT = BB*TT;          // 512
    const long zTot = (long)BT*G4;  // 1,048,576

    // ---- GCN layer 1 ----
    hgemm<true><<<dim3(1, NN_/HBM, BT), 256, HSMEM>>>(pX16, pW116, nullptr, nullptr, pHw16,
        NN_, HH, CC, sX, BT, (long)CC*HH, TT, 0, 1, sX, 1, 0);
    hgemm<true><<<dim3(1, NN_/HBM, BT), 256, HSMEM>>>(pM16, pHw16, b1, pTmp, nullptr,
        NN_, HH, NN_, 0, 1, sX, BT, HH, TT, sX, 1, 0);
    graphnorm_kernel<false><<<(int)(TNH/256), 256>>>(pTmp, x, nullptr,
        gn1w, gn1b, gn1m, pH116);

    // ---- GCN layer 2 ----
    hgemm<true><<<dim3(1, NN_/HBM, BT), 256, HSMEM>>>(pH116, pW216, nullptr, nullptr, pHw16,
        NN_, HH, HH, sX, BT, (long)HH*HH, TT, 0, 1, sX, 1, 0);
    hgemm<true><<<dim3(1, NN_/HBM, BT), 256, HSMEM>>>(pM16, pHw16, b2, pTmp, nullptr,
        NN_, HH, NN_, 0, 1, sX, BT, HH, TT, sX, 1, 0);
    graphnorm_kernel<true><<<(int)(TNH/256), 256>>>(pTmp, nullptr, pH116,
        gn2w, gn2b, gn2m, pH216);

    // ---- LSTM layer 0: Z0 GEMM (split-K=16), reduce, persistent recurrence ----
    hgemm<false><<<dim3(G4/HBN, BT/HBM, SPLITK0), 256, HSMEM>>>(pH216, pWih016, nullptr, pTmp, nullptr,
        BT, G4, DD, 0, 1, 0, 1, 0, 1, 0, SPLITK0, zTot);
    reduce_bias_kernel<<<(int)(zTot/256), 256>>>(pTmp, bih0, pZ0, zTot, zTot, SPLITK0);
    lstm_persistent<true><<<LBLK, LTHR>>>(pZ0, Whh0, bhh0, pHA0, pHB0, pY016, pBars);

    // ---- LSTM layer 1 ----
    hgemm<false><<<dim3(G4/HBN, BT/HBM, SPLITK1), 256, HSMEM>>>(pY016, pWih116, nullptr, pTmp, nullptr,
        BT, G4, HLL, 0, 1, 0, 1, 0, 1, 0, SPLITK1, zTot);
    reduce_bias_kernel<<<(int)(zTot/256), 256>>>(pTmp, bih1, pZ1, zTot, zTot, SPLITK1);
    lstm_persistent<false><<<LBLK, LTHR>>>(pZ1, Whh1, bhh1, pHA1, pHB1, nullptr,
                                           pBars + NBAR*BARSTR);

    // ---- projection ----
    proj_kernel<<<1, 128>>>(pHA1, Wp, bp, out);
}